// round 4
// baseline (speedup 1.0000x reference)
#include <cuda_runtime.h>
#include <cstdint>

#define B_  8
#define C_  64
#define T_  12
#define N_  512
#define G_  (B_ * T_)      // 96
#define H_  4
#define CO_ 64
#define HC_ (H_ * CO_)     // 256
#define NEG_SLOPE 0.2f
#define EMAX 16384

typedef unsigned long long ull;

// ---------------- device scratch ----------------
__device__ float g_xt[(size_t)G_ * N_ * C_];     // [G,N,64]
__device__ float g_z [(size_t)G_ * N_ * HC_];    // [G,N,256]
__device__ float g_asrc[(size_t)G_ * N_ * H_];   // [G,N,4]
__device__ float g_adst[(size_t)G_ * N_ * H_];
__device__ float g_u[2 * H_ * C_];               // [src/dst][h][c]
__device__ float g_Wt[HC_ * CO_];                // Wt[h*64+c][co] = 0.25*W[c][h*64+co]
__device__ int   g_rowptr[N_ + 1];
__device__ int   g_col[EMAX];

__device__ __forceinline__ float lrelu(float x) {
    return x > 0.0f ? x : NEG_SLOPE * x;
}
__device__ __forceinline__ ull pack2(float lo, float hi) {
    ull d;
    asm("mov.b64 %0, {%1, %2};" : "=l"(d) : "r"(__float_as_uint(lo)), "r"(__float_as_uint(hi)));
    return d;
}
__device__ __forceinline__ void unpack2(ull v, float& lo, float& hi) {
    unsigned a, b;
    asm("mov.b64 {%0, %1}, %2;" : "=r"(a), "=r"(b) : "l"(v));
    lo = __uint_as_float(a); hi = __uint_as_float(b);
}
__device__ __forceinline__ ull fma2(ull a, ull b, ull c) {
    ull d;
    asm("fma.rn.f32x2 %0, %1, %2, %3;" : "=l"(d) : "l"(a), "l"(b), "l"(c));
    return d;
}

// ============================================================
// K0: setup. block 0: CSR build. block 1: prep u + Wt. 512 thr.
// ============================================================
__global__ void setup_kernel(const int* __restrict__ ei, int E,
                             const float* __restrict__ W,
                             const float* __restrict__ att_src,
                             const float* __restrict__ att_dst) {
    int tid = threadIdx.x;
    if (blockIdx.x == 0) {
        __shared__ int cnt[N_];
        __shared__ int cur[N_];
        __shared__ int wsum[16];
        cnt[tid] = 0;
        __syncthreads();
        const int* dst = ei + E;
        for (int e = tid; e < E; e += N_) atomicAdd(&cnt[dst[e]], 1);
        __syncthreads();

        int v = cnt[tid];
        int lane = tid & 31, wid = tid >> 5;
        int inc = v;
        #pragma unroll
        for (int o = 1; o < 32; o <<= 1) {
            int u = __shfl_up_sync(0xffffffffu, inc, o);
            if (lane >= o) inc += u;
        }
        if (lane == 31) wsum[wid] = inc;
        __syncthreads();
        if (wid == 0 && lane < 16) {
            int ws = wsum[lane];
            int wi = ws;
            #pragma unroll
            for (int o = 1; o < 16; o <<= 1) {
                int u = __shfl_up_sync(0x0000ffffu, wi, o);
                if (lane >= o) wi += u;
            }
            wsum[lane] = wi - ws;
        }
        __syncthreads();
        int excl = inc - v + wsum[wid];
        g_rowptr[tid] = excl;
        cur[tid] = excl;
        if (tid == N_ - 1) g_rowptr[N_] = excl + v;
        __syncthreads();

        for (int e = tid; e < E; e += N_) {
            int d = dst[e];
            int p = atomicAdd(&cur[d], 1);
            g_col[p] = ei[e];
        }
    } else {
        __shared__ float satt[2 * H_ * CO_];
        satt[tid] = (tid < 256) ? att_src[tid] : att_dst[tid - 256];
        __syncthreads();

        // u[p][h][c]
        {
            int k = tid;                 // 512 = 2*4*64
            int p = k >> 8;
            int h = (k >> 6) & 3;
            int c = k & 63;
            const float* wrow = W + (size_t)c * HC_ + h * CO_;
            const float* av = satt + p * 256 + h * CO_;
            float s = 0.0f;
            #pragma unroll 16
            for (int co = 0; co < CO_; co++) s += wrow[co] * av[co];
            g_u[k] = s;
        }
        // Wt
        for (int idx = tid; idx < HC_ * CO_; idx += 512) {
            int kk = idx >> 6;
            int co = idx & 63;
            int h = kk >> 6, c = kk & 63;
            g_Wt[idx] = 0.25f * W[(size_t)c * HC_ + h * CO_ + co];
        }
    }
}

// ============================================================
// K1: per g: transpose x -> xt, asrc/adst = x . u
// grid (4, 96), block 256.
// ============================================================
__global__ void xt_asrc_kernel(const float* __restrict__ x) {
    __shared__ float xs[64][129];
    __shared__ float su[8][64];
    int g  = blockIdx.y;
    int n0 = blockIdx.x * 128;
    int b  = g / T_;
    int t  = g - b * T_;
    int tid = threadIdx.x;

    for (int i = tid; i < 512; i += 256) su[i >> 6][i & 63] = g_u[i];
    #pragma unroll
    for (int i = tid; i < 64 * 32; i += 256) {
        int c = i >> 5, q = i & 31;
        float4 v = *(const float4*)(x + (((size_t)b * C_ + c) * T_ + t) * N_ + n0 + q * 4);
        xs[c][q * 4 + 0] = v.x; xs[c][q * 4 + 1] = v.y;
        xs[c][q * 4 + 2] = v.z; xs[c][q * 4 + 3] = v.w;
    }
    __syncthreads();

    {
        int n = tid & 127;
        int p = tid >> 7;
        float a0 = 0.f, a1 = 0.f, a2 = 0.f, a3 = 0.f;
        #pragma unroll 16
        for (int c = 0; c < 64; c++) {
            float xv = xs[c][n];
            a0 = fmaf(xv, su[p * 4 + 0][c], a0);
            a1 = fmaf(xv, su[p * 4 + 1][c], a1);
            a2 = fmaf(xv, su[p * 4 + 2][c], a2);
            a3 = fmaf(xv, su[p * 4 + 3][c], a3);
        }
        float* dstp = (p == 0 ? g_asrc : g_adst) + ((size_t)g * N_ + n0 + n) * H_;
        dstp[0] = a0; dstp[1] = a1; dstp[2] = a2; dstp[3] = a3;
    }

    #pragma unroll
    for (int i = tid; i < 128 * 16; i += 256) {
        int n = i >> 4, q = i & 15;
        float4 v = {xs[q * 4 + 0][n], xs[q * 4 + 1][n], xs[q * 4 + 2][n], xs[q * 4 + 3][n]};
        *(float4*)(g_xt + ((size_t)g * N_ + n0 + n) * C_ + q * 4) = v;
    }
}

// ============================================================
// K2: aggregate in x-space, warp per (g,dst).
// smem-staged packed weights + f32x2 FMA. grid (64,96), block 256.
// ============================================================
__global__ void __launch_bounds__(256) aggregate_kernel() {
    __shared__ float4 s_as[N_];
    __shared__ ull    s_wp[8][32][4];   // (w,w) packed per head
    __shared__ int    s_src[8][32];
    int g    = blockIdx.y;
    int tid  = threadIdx.x;
    int warp = tid >> 5, lane = tid & 31;

    const float4* asrc_g = (const float4*)(g_asrc + (size_t)g * N_ * H_);
    for (int i = tid; i < N_; i += 256) s_as[i] = asrc_g[i];
    __syncthreads();

    int dst   = (blockIdx.x << 3) + warp;
    int start = g_rowptr[dst];
    int end   = g_rowptr[dst + 1];

    float4 ad = *(const float4*)(g_adst + ((size_t)g * N_ + dst) * H_);
    float4 sa = s_as[dst];
    float ws0 = __expf(lrelu(sa.x + ad.x));
    float ws1 = __expf(lrelu(sa.y + ad.y));
    float ws2 = __expf(lrelu(sa.z + ad.z));
    float ws3 = __expf(lrelu(sa.w + ad.w));

    const ull* xgu = (const ull*)(g_xt + (size_t)g * N_ * C_);  // 32 ull per row

    // self-loop init
    ull xdv = xgu[(size_t)dst * 32 + lane];
    ull acc0 = fma2(pack2(ws0, ws0), xdv, 0ULL);
    ull acc1 = fma2(pack2(ws1, ws1), xdv, 0ULL);
    ull acc2 = fma2(pack2(ws2, ws2), xdv, 0ULL);
    ull acc3 = fma2(pack2(ws3, ws3), xdv, 0ULL);

    float p0 = 0.f, p1 = 0.f, p2 = 0.f, p3 = 0.f;

    for (int base = start; base < end; base += 32) {
        int e = base + lane;
        int src = 0;
        float w0 = 0.f, w1 = 0.f, w2 = 0.f, w3 = 0.f;
        if (e < end) {
            src = g_col[e];
            float4 a = s_as[src];
            w0 = __expf(lrelu(a.x + ad.x));
            w1 = __expf(lrelu(a.y + ad.y));
            w2 = __expf(lrelu(a.z + ad.z));
            w3 = __expf(lrelu(a.w + ad.w));
        }
        p0 += w0; p1 += w1; p2 += w2; p3 += w3;
        ulonglong2 pA, pB;
        pA.x = pack2(w0, w0); pA.y = pack2(w1, w1);
        pB.x = pack2(w2, w2); pB.y = pack2(w3, w3);
        *(ulonglong2*)&s_wp[warp][lane][0] = pA;
        *(ulonglong2*)&s_wp[warp][lane][2] = pB;
        s_src[warp][lane] = src;
        __syncwarp();

        int cnt = min(32, end - base);
        int sj = s_src[warp][0];
        ull xv = xgu[(size_t)sj * 32 + lane];
        for (int j = 0; j < cnt; j++) {
            int jn = min(j + 1, cnt - 1);
            int sn = s_src[warp][jn];
            ull xn = xgu[(size_t)sn * 32 + lane];
            ulonglong2 wA = *(const ulonglong2*)&s_wp[warp][j][0];
            ulonglong2 wB = *(const ulonglong2*)&s_wp[warp][j][2];
            acc0 = fma2(wA.x, xv, acc0);
            acc1 = fma2(wA.y, xv, acc1);
            acc2 = fma2(wB.x, xv, acc2);
            acc3 = fma2(wB.y, xv, acc3);
            xv = xn;
        }
        __syncwarp();
    }

    #pragma unroll
    for (int o = 16; o > 0; o >>= 1) {
        p0 += __shfl_xor_sync(0xffffffffu, p0, o);
        p1 += __shfl_xor_sync(0xffffffffu, p1, o);
        p2 += __shfl_xor_sync(0xffffffffu, p2, o);
        p3 += __shfl_xor_sync(0xffffffffu, p3, o);
    }
    float i0 = 1.0f / (p0 + ws0);
    float i1 = 1.0f / (p1 + ws1);
    float i2 = 1.0f / (p2 + ws2);
    float i3 = 1.0f / (p3 + ws3);

    float lo, hi;
    float* zp = g_z + ((size_t)g * N_ + dst) * HC_ + 2 * lane;
    unpack2(acc0, lo, hi); *(float2*)(zp +   0) = make_float2(lo * i0, hi * i0);
    unpack2(acc1, lo, hi); *(float2*)(zp +  64) = make_float2(lo * i1, hi * i1);
    unpack2(acc2, lo, hi); *(float2*)(zp + 128) = make_float2(lo * i2, hi * i2);
    unpack2(acc3, lo, hi); *(float2*)(zp + 192) = make_float2(lo * i3, hi * i3);
}

// ============================================================
// K3: out = z @ Wt + bias -> [B,Co,T,N]. f32x2 with packed z.
// grid (8, 96), block 256.
// ============================================================
__global__ void __launch_bounds__(256) gemm2_kernel(const float* __restrict__ bias,
                                                    float* __restrict__ out) {
    __shared__ __align__(16) char s_union[64 * 64 * 8];   // zs (packed) / os
    __shared__ float ws[64][64];
    ull  (*zs)[64] = (ull(*)[64])s_union;     // [n][k] duplicated pairs
    float (*os)[68] = (float(*)[68])s_union;  // [co][n]

    int g  = blockIdx.y;
    int n0 = blockIdx.x * 64;
    int b  = g / T_;
    int t  = g - b * T_;
    int tid = threadIdx.x;
    int ty = tid >> 4;   // n quad
    int tx = tid & 15;   // co quad

    ull acc[4][2];
    #pragma unroll
    for (int i = 0; i < 4; i++) { acc[i][0] = 0ULL; acc[i][1] = 0ULL; }

    for (int kk = 0; kk < 4; kk++) {
        __syncthreads();
        #pragma unroll
        for (int i = tid; i < 64 * 16; i += 256) {
            int n = i >> 4, q = i & 15;
            float4 v = *(const float4*)(g_z + ((size_t)g * N_ + n0 + n) * HC_ + kk * 64 + q * 4);
            ulonglong2 zA, zB;
            zA.x = pack2(v.x, v.x); zA.y = pack2(v.y, v.y);
            zB.x = pack2(v.z, v.z); zB.y = pack2(v.w, v.w);
            *(ulonglong2*)&zs[n][q * 4]     = zA;
            *(ulonglong2*)&zs[n][q * 4 + 2] = zB;
            float4 w = *(const float4*)(g_Wt + (size_t)(kk * 64 + n) * CO_ + q * 4);
            *(float4*)&ws[n][q * 4] = w;
        }
        __syncthreads();

        #pragma unroll 8
        for (int c0 = 0; c0 < 64; c0 += 2) {
            ulonglong2 za0 = *(const ulonglong2*)&zs[ty * 4 + 0][c0];
            ulonglong2 za1 = *(const ulonglong2*)&zs[ty * 4 + 1][c0];
            ulonglong2 za2 = *(const ulonglong2*)&zs[ty * 4 + 2][c0];
            ulonglong2 za3 = *(const ulonglong2*)&zs[ty * 4 + 3][c0];
            ulonglong2 w0 = *(const ulonglong2*)&ws[c0][tx * 4];
            ulonglong2 w1 = *(const ulonglong2*)&ws[c0 + 1][tx * 4];
            acc[0][0] = fma2(za0.x, w0.x, acc[0][0]); acc[0][1] = fma2(za0.x, w0.y, acc[0][1]);
            acc[1][0] = fma2(za1.x, w0.x, acc[1][0]); acc[1][1] = fma2(za1.x, w0.y, acc[1][1]);
            acc[2][0] = fma2(za2.x, w0.x, acc[2][0]); acc[2][1] = fma2(za2.x, w0.y, acc[2][1]);
            acc[3][0] = fma2(za3.x, w0.x, acc[3][0]); acc[3][1] = fma2(za3.x, w0.y, acc[3][1]);
            acc[0][0] = fma2(za0.y, w1.x, acc[0][0]); acc[0][1] = fma2(za0.y, w1.y, acc[0][1]);
            acc[1][0] = fma2(za1.y, w1.x, acc[1][0]); acc[1][1] = fma2(za1.y, w1.y, acc[1][1]);
            acc[2][0] = fma2(za2.y, w1.x, acc[2][0]); acc[2][1] = fma2(za2.y, w1.y, acc[2][1]);
            acc[3][0] = fma2(za3.y, w1.x, acc[3][0]); acc[3][1] = fma2(za3.y, w1.y, acc[3][1]);
        }
    }
    __syncthreads();   // zs dead; reuse as os

    #pragma unroll
    for (int i = 0; i < 4; i++) {
        int n = ty * 4 + i;
        #pragma unroll
        for (int jp = 0; jp < 2; jp++) {
            float lo, hi;
            unpack2(acc[i][jp], lo, hi);
            int co = tx * 4 + jp * 2;
            os[co][n]     = lo + __ldg(&bias[co]);
            os[co + 1][n] = hi + __ldg(&bias[co + 1]);
        }
    }
    __syncthreads();

    #pragma unroll
    for (int i = tid; i < 64 * 16; i += 256) {
        int co = i >> 4, q = i & 15;
        float4 v = *(const float4*)&os[co][q * 4];
        *(float4*)(out + (((size_t)b * CO_ + co) * T_ + t) * N_ + n0 + q * 4) = v;
    }
}

// ============================================================
extern "C" void kernel_launch(void* const* d_in, const int* in_sizes, int n_in,
                              void* d_out, int out_size) {
    const float* x        = (const float*)d_in[0];
    const int*   ei       = (const int*)  d_in[1];
    const float* W        = (const float*)d_in[2];
    const float* att_src  = (const float*)d_in[3];
    const float* att_dst  = (const float*)d_in[4];
    const float* bias     = (const float*)d_in[5];
    float*       out      = (float*)d_out;
    int E = in_sizes[1] / 2;

    setup_kernel<<<2, 512>>>(ei, E, W, att_src, att_dst);
    xt_asrc_kernel<<<dim3(N_ / 128, G_), 256>>>(x);
    aggregate_kernel<<<dim3(N_ / 8, G_), 256>>>();
    gemm2_kernel<<<dim3(N_ / 64, G_), 256>>>(bias, out);
}

// round 5
// speedup vs baseline: 1.1031x; 1.1031x over previous
#include <cuda_runtime.h>
#include <cstdint>

#define B_  8
#define C_  64
#define T_  12
#define N_  512
#define G_  (B_ * T_)      // 96
#define H_  4
#define CO_ 64
#define HC_ (H_ * CO_)     // 256
#define NEG_SLOPE 0.2f
#define EMAX 16384

typedef unsigned long long ull;

// ---------------- device scratch ----------------
__device__ float g_xt[(size_t)G_ * N_ * C_];     // [G,N,64]
__device__ float g_z [(size_t)G_ * N_ * HC_];    // [G,N,256]
__device__ float g_asrc[(size_t)G_ * N_ * H_];   // [G,N,4]
__device__ float g_adst[(size_t)G_ * N_ * H_];
__device__ float g_u[2 * H_ * C_];               // [src/dst][h][c]
__device__ ull   g_Wtp[128 * CO_];               // [kp][co] = (Wt[2kp][co], Wt[2kp+1][co])
__device__ int   g_rowptr[N_ + 1];
__device__ int   g_col[EMAX];

__device__ __forceinline__ float lrelu(float x) {
    return x > 0.0f ? x : NEG_SLOPE * x;
}
__device__ __forceinline__ ull pack2(float lo, float hi) {
    ull d;
    asm("mov.b64 %0, {%1, %2};" : "=l"(d) : "r"(__float_as_uint(lo)), "r"(__float_as_uint(hi)));
    return d;
}
__device__ __forceinline__ void unpack2(ull v, float& lo, float& hi) {
    unsigned a, b;
    asm("mov.b64 {%0, %1}, %2;" : "=r"(a), "=r"(b) : "l"(v));
    lo = __uint_as_float(a); hi = __uint_as_float(b);
}
__device__ __forceinline__ ull fma2(ull a, ull b, ull c) {
    ull d;
    asm("fma.rn.f32x2 %0, %1, %2, %3;" : "=l"(d) : "l"(a), "l"(b), "l"(c));
    return d;
}

// ============================================================
// K0: setup. block 0: CSR build. block 1: prep u + Wtp. 512 thr.
// ============================================================
__global__ void setup_kernel(const int* __restrict__ ei, int E,
                             const float* __restrict__ W,
                             const float* __restrict__ att_src,
                             const float* __restrict__ att_dst) {
    int tid = threadIdx.x;
    if (blockIdx.x == 0) {
        __shared__ int cnt[N_];
        __shared__ int cur[N_];
        __shared__ int wsum[16];
        cnt[tid] = 0;
        __syncthreads();
        const int* dst = ei + E;
        for (int e = tid; e < E; e += N_) atomicAdd(&cnt[dst[e]], 1);
        __syncthreads();

        int v = cnt[tid];
        int lane = tid & 31, wid = tid >> 5;
        int inc = v;
        #pragma unroll
        for (int o = 1; o < 32; o <<= 1) {
            int u = __shfl_up_sync(0xffffffffu, inc, o);
            if (lane >= o) inc += u;
        }
        if (lane == 31) wsum[wid] = inc;
        __syncthreads();
        if (wid == 0 && lane < 16) {
            int ws = wsum[lane];
            int wi = ws;
            #pragma unroll
            for (int o = 1; o < 16; o <<= 1) {
                int u = __shfl_up_sync(0x0000ffffu, wi, o);
                if (lane >= o) wi += u;
            }
            wsum[lane] = wi - ws;
        }
        __syncthreads();
        int excl = inc - v + wsum[wid];
        g_rowptr[tid] = excl;
        cur[tid] = excl;
        if (tid == N_ - 1) g_rowptr[N_] = excl + v;
        __syncthreads();

        for (int e = tid; e < E; e += N_) {
            int d = dst[e];
            int p = atomicAdd(&cur[d], 1);
            g_col[p] = ei[e];
        }
    } else {
        __shared__ float satt[2 * H_ * CO_];
        satt[tid] = (tid < 256) ? att_src[tid] : att_dst[tid - 256];
        __syncthreads();

        // u[p][h][c]
        {
            int k = tid;                 // 512 = 2*4*64
            int p = k >> 8;
            int h = (k >> 6) & 3;
            int c = k & 63;
            const float* wrow = W + (size_t)c * HC_ + h * CO_;
            const float* av = satt + p * 256 + h * CO_;
            float s = 0.0f;
            #pragma unroll 16
            for (int co = 0; co < CO_; co++) s += wrow[co] * av[co];
            g_u[k] = s;
        }
        // Wtp: paired-k packed weights. Wt[k][co] = 0.25*W[c][h*64+co], k=h*64+c
        for (int idx = tid; idx < 128 * CO_; idx += 512) {
            int kp = idx >> 6;
            int co = idx & 63;
            int k0 = kp * 2;
            int h = k0 >> 6, c0 = k0 & 63;
            float w0 = 0.25f * W[(size_t)c0 * HC_ + h * CO_ + co];
            float w1 = 0.25f * W[(size_t)(c0 + 1) * HC_ + h * CO_ + co];
            g_Wtp[idx] = pack2(w0, w1);
        }
    }
}

// ============================================================
// K1: per g: transpose x -> xt, asrc/adst = x . u
// grid (4, 96), block 256.
// ============================================================
__global__ void xt_asrc_kernel(const float* __restrict__ x) {
    __shared__ float xs[64][129];
    __shared__ float su[8][64];
    int g  = blockIdx.y;
    int n0 = blockIdx.x * 128;
    int b  = g / T_;
    int t  = g - b * T_;
    int tid = threadIdx.x;

    for (int i = tid; i < 512; i += 256) su[i >> 6][i & 63] = g_u[i];
    #pragma unroll
    for (int i = tid; i < 64 * 32; i += 256) {
        int c = i >> 5, q = i & 31;
        float4 v = *(const float4*)(x + (((size_t)b * C_ + c) * T_ + t) * N_ + n0 + q * 4);
        xs[c][q * 4 + 0] = v.x; xs[c][q * 4 + 1] = v.y;
        xs[c][q * 4 + 2] = v.z; xs[c][q * 4 + 3] = v.w;
    }
    __syncthreads();

    {
        int n = tid & 127;
        int p = tid >> 7;
        float a0 = 0.f, a1 = 0.f, a2 = 0.f, a3 = 0.f;
        #pragma unroll 16
        for (int c = 0; c < 64; c++) {
            float xv = xs[c][n];
            a0 = fmaf(xv, su[p * 4 + 0][c], a0);
            a1 = fmaf(xv, su[p * 4 + 1][c], a1);
            a2 = fmaf(xv, su[p * 4 + 2][c], a2);
            a3 = fmaf(xv, su[p * 4 + 3][c], a3);
        }
        float* dstp = (p == 0 ? g_asrc : g_adst) + ((size_t)g * N_ + n0 + n) * H_;
        dstp[0] = a0; dstp[1] = a1; dstp[2] = a2; dstp[3] = a3;
    }

    #pragma unroll
    for (int i = tid; i < 128 * 16; i += 256) {
        int n = i >> 4, q = i & 15;
        float4 v = {xs[q * 4 + 0][n], xs[q * 4 + 1][n], xs[q * 4 + 2][n], xs[q * 4 + 3][n]};
        *(float4*)(g_xt + ((size_t)g * N_ + n0 + n) * C_ + q * 4) = v;
    }
}

// ============================================================
// K2: aggregate in x-space, warp per (g,dst). (unchanged from R4)
// ============================================================
__global__ void __launch_bounds__(256) aggregate_kernel() {
    __shared__ float4 s_as[N_];
    __shared__ ull    s_wp[8][32][4];
    __shared__ int    s_src[8][32];
    int g    = blockIdx.y;
    int tid  = threadIdx.x;
    int warp = tid >> 5, lane = tid & 31;

    const float4* asrc_g = (const float4*)(g_asrc + (size_t)g * N_ * H_);
    for (int i = tid; i < N_; i += 256) s_as[i] = asrc_g[i];
    __syncthreads();

    int dst   = (blockIdx.x << 3) + warp;
    int start = g_rowptr[dst];
    int end   = g_rowptr[dst + 1];

    float4 ad = *(const float4*)(g_adst + ((size_t)g * N_ + dst) * H_);
    float4 sa = s_as[dst];
    float ws0 = __expf(lrelu(sa.x + ad.x));
    float ws1 = __expf(lrelu(sa.y + ad.y));
    float ws2 = __expf(lrelu(sa.z + ad.z));
    float ws3 = __expf(lrelu(sa.w + ad.w));

    const ull* xgu = (const ull*)(g_xt + (size_t)g * N_ * C_);

    ull xdv = xgu[(size_t)dst * 32 + lane];
    ull acc0 = fma2(pack2(ws0, ws0), xdv, 0ULL);
    ull acc1 = fma2(pack2(ws1, ws1), xdv, 0ULL);
    ull acc2 = fma2(pack2(ws2, ws2), xdv, 0ULL);
    ull acc3 = fma2(pack2(ws3, ws3), xdv, 0ULL);

    float p0 = 0.f, p1 = 0.f, p2 = 0.f, p3 = 0.f;

    for (int base = start; base < end; base += 32) {
        int e = base + lane;
        int src = 0;
        float w0 = 0.f, w1 = 0.f, w2 = 0.f, w3 = 0.f;
        if (e < end) {
            src = g_col[e];
            float4 a = s_as[src];
            w0 = __expf(lrelu(a.x + ad.x));
            w1 = __expf(lrelu(a.y + ad.y));
            w2 = __expf(lrelu(a.z + ad.z));
            w3 = __expf(lrelu(a.w + ad.w));
        }
        p0 += w0; p1 += w1; p2 += w2; p3 += w3;
        ulonglong2 pA, pB;
        pA.x = pack2(w0, w0); pA.y = pack2(w1, w1);
        pB.x = pack2(w2, w2); pB.y = pack2(w3, w3);
        *(ulonglong2*)&s_wp[warp][lane][0] = pA;
        *(ulonglong2*)&s_wp[warp][lane][2] = pB;
        s_src[warp][lane] = src;
        __syncwarp();

        int cnt = min(32, end - base);
        int sj = s_src[warp][0];
        ull xv = xgu[(size_t)sj * 32 + lane];
        for (int j = 0; j < cnt; j++) {
            int jn = min(j + 1, cnt - 1);
            int sn = s_src[warp][jn];
            ull xn = xgu[(size_t)sn * 32 + lane];
            ulonglong2 wA = *(const ulonglong2*)&s_wp[warp][j][0];
            ulonglong2 wB = *(const ulonglong2*)&s_wp[warp][j][2];
            acc0 = fma2(wA.x, xv, acc0);
            acc1 = fma2(wA.y, xv, acc1);
            acc2 = fma2(wB.x, xv, acc2);
            acc3 = fma2(wB.y, xv, acc3);
            xv = xn;
        }
        __syncwarp();
    }

    #pragma unroll
    for (int o = 16; o > 0; o >>= 1) {
        p0 += __shfl_xor_sync(0xffffffffu, p0, o);
        p1 += __shfl_xor_sync(0xffffffffu, p1, o);
        p2 += __shfl_xor_sync(0xffffffffu, p2, o);
        p3 += __shfl_xor_sync(0xffffffffu, p3, o);
    }
    float i0 = 1.0f / (p0 + ws0);
    float i1 = 1.0f / (p1 + ws1);
    float i2 = 1.0f / (p2 + ws2);
    float i3 = 1.0f / (p3 + ws3);

    float lo, hi;
    float* zp = g_z + ((size_t)g * N_ + dst) * HC_ + 2 * lane;
    unpack2(acc0, lo, hi); *(float2*)(zp +   0) = make_float2(lo * i0, hi * i0);
    unpack2(acc1, lo, hi); *(float2*)(zp +  64) = make_float2(lo * i1, hi * i1);
    unpack2(acc2, lo, hi); *(float2*)(zp + 128) = make_float2(lo * i2, hi * i2);
    unpack2(acc3, lo, hi); *(float2*)(zp + 192) = make_float2(lo * i3, hi * i3);
}

// ============================================================
// K3: out = z @ Wt + bias -> [B,Co,T,N].
// Broadcast-z LDS.64 pairs + paired-k packed weights.
// grid (8, 96), block 256 (8 warps; warp = 8 n rows x 64 co).
// ============================================================
#define SF_PAD 68
__global__ void __launch_bounds__(256) gemm2_kernel(const float* __restrict__ bias,
                                                    float* __restrict__ out) {
    __shared__ __align__(16) char sm[64 * SF_PAD * 4 + 32 * 64 * 8];  // 17408 + 16384
    float (*s_f)[SF_PAD] = (float(*)[SF_PAD])sm;            // [n][k] chunk
    ull   (*s_w)[64]     = (ull(*)[64])(sm + 64 * SF_PAD * 4);  // [kp][co]
    float (*os)[SF_PAD]  = (float(*)[SF_PAD])sm;             // reuse: [co][n]

    int g  = blockIdx.y;
    int n0 = blockIdx.x * 64;
    int b  = g / T_;
    int t  = g - b * T_;
    int tid = threadIdx.x;
    int w = tid >> 5, lane = tid & 31;

    ull acc[8][2];
    #pragma unroll
    for (int i = 0; i < 8; i++) { acc[i][0] = 0ULL; acc[i][1] = 0ULL; }

    const float* zrow0 = g_z + ((size_t)g * N_ + n0) * HC_;

    for (int kk = 0; kk < 4; kk++) {
        __syncthreads();
        // stage z chunk [64 n][64 k], coalesced
        #pragma unroll
        for (int i = tid; i < 64 * 16; i += 256) {
            int n = i >> 4, q = i & 15;
            float4 v = *(const float4*)(zrow0 + (size_t)n * HC_ + kk * 64 + q * 4);
            *(float4*)&s_f[n][q * 4] = v;
        }
        // stage w chunk [32 kp][64 co] ull
        #pragma unroll
        for (int i = tid; i < 32 * 32; i += 256) {
            int kp = i >> 5, c2 = i & 31;
            ulonglong2 v = *(const ulonglong2*)(g_Wtp + (size_t)(kk * 32 + kp) * CO_ + c2 * 2);
            *(ulonglong2*)&s_w[kp][c2 * 2] = v;
        }
        __syncthreads();

        #pragma unroll 4
        for (int kp = 0; kp < 32; kp++) {
            ulonglong2 wv = *(const ulonglong2*)&s_w[kp][lane * 2];
            #pragma unroll
            for (int i = 0; i < 8; i++) {
                ull zv = *(const ull*)&s_f[w * 8 + i][kp * 2];   // broadcast LDS.64, already a pair
                acc[i][0] = fma2(zv, wv.x, acc[i][0]);
                acc[i][1] = fma2(zv, wv.y, acc[i][1]);
            }
        }
    }
    __syncthreads();   // s_f dead; reuse as os

    // epilogue: lane holds co {2*lane, 2*lane+1} for 8 n rows
    #pragma unroll
    for (int i = 0; i < 8; i++) {
        float lo, hi;
        unpack2(acc[i][0], lo, hi);
        os[lane * 2][w * 8 + i] = lo + hi;
        unpack2(acc[i][1], lo, hi);
        os[lane * 2 + 1][w * 8 + i] = lo + hi;
    }
    __syncthreads();

    // coalesced write out[b, co, t, n0..] with bias
    #pragma unroll
    for (int i = tid; i < 64 * 16; i += 256) {
        int co = i >> 4, q = i & 15;
        float bv = __ldg(&bias[co]);
        float4 v = *(const float4*)&os[co][q * 4];
        v.x += bv; v.y += bv; v.z += bv; v.w += bv;
        *(float4*)(out + (((size_t)b * CO_ + co) * T_ + t) * N_ + n0 + q * 4) = v;
    }
}

// ============================================================
extern "C" void kernel_launch(void* const* d_in, const int* in_sizes, int n_in,
                              void* d_out, int out_size) {
    const float* x        = (const float*)d_in[0];
    const int*   ei       = (const int*)  d_in[1];
    const float* W        = (const float*)d_in[2];
    const float* att_src  = (const float*)d_in[3];
    const float* att_dst  = (const float*)d_in[4];
    const float* bias     = (const float*)d_in[5];
    float*       out      = (float*)d_out;
    int E = in_sizes[1] / 2;

    setup_kernel<<<2, 512>>>(ei, E, W, att_src, att_dst);
    xt_asrc_kernel<<<dim3(N_ / 128, G_), 256>>>(x);
    aggregate_kernel<<<dim3(N_ / 8, G_), 256>>>();
    gemm2_kernel<<<dim3(N_ / 64, G_), 256>>>(bias, out);
}